// round 15
// baseline (speedup 1.0000x reference)
#include <cuda_runtime.h>
#include <cuda_bf16.h>
#include <math.h>

#define BD 4
#define LL 4096
#define PX (BD*LL)        // 16384 pixels
#define CM 192
#define DI 384
#define RK 12
#define NS 16
#define NC 8              // scan chunks
#define LC (LL/NC)        // 512
#define TT 64             // scan sub-tile

// ---------------- scratch (device globals; no mallocs allowed) ----------------
__device__ __nv_bfloat16 d_xnb [PX*CM];          // LN out, bf16
__device__ __nv_bfloat16 d_lowb[PX*CM];          // low, bf16
__device__ float d_xz   [(size_t)PX*2*DI];
__device__ __nv_bfloat16 d_lowpb[(size_t)PX*DI]; // in_proj_low out, bf16
__device__ __nv_bfloat16 d_xsb [(size_t)PX*DI];  // conv out, bf16 pixel-major
__device__ __nv_bfloat16 d_utb [(size_t)BD*DI*LL]; // u channel-major, bf16
__device__ float d_xdbl [PX*64];
__device__ float d_ldbl [PX*64];
__device__ float d_dts0 [PX*16];
__device__ float d_Bs0  [PX*16];
__device__ float d_Cs0  [PX*16];
__device__ float d_dts1 [PX*16];
__device__ float d_Bs1  [PX*16];
__device__ float d_Cs1  [PX*16];
__device__ float d_y    [(size_t)PX*DI];
__device__ __nv_bfloat16 d_gatedb[(size_t)PX*DI];
__device__ __nv_bfloat16 d_W1b [2*DI*CM];        // in_proj   [768][192] bf16
__device__ __nv_bfloat16 d_W2b [DI*CM];          // in_proj_low [384][192]
__device__ __nv_bfloat16 d_W3b [CM*DI];          // out_proj  [192][384]
__device__ __nv_bfloat16 d_Wtxb [64*DI];         // x_proj    [64pad][384]
__device__ __nv_bfloat16 d_Wtxlb[64*DI];         // x_proj_low[64pad][384]
__device__ float d_hfin [BD*NC*DI*NS];
__device__ float d_dsum [BD*NC*DI];
__device__ float d_hin  [BD*NC*DI*NS];

// ---------------- bf16 tensor-core GEMM, BK=64, ldmatrix: C = A·Bw^T ----------------
__global__ __launch_bounds__(256) void k_gemm_bf16(
        const __nv_bfloat16* __restrict__ A, const __nv_bfloat16* __restrict__ Bw,
        float* __restrict__ C, __nv_bfloat16* __restrict__ Cb,
        int K, int N, const float* __restrict__ resid) {
    __shared__ unsigned As[128*36];   // [m][kp], row stride 36 (32+pad4)
    __shared__ unsigned Bs[64*36];
    int m0 = blockIdx.y*128, n0 = blockIdx.x*64;
    int tid = threadIdx.x, lane = tid&31, warp = tid>>5;
    int wm = (warp&3)*32, wn = (warp>>2)*32;
    float acc[2][4][4];
    #pragma unroll
    for (int i=0;i<2;i++)
        #pragma unroll
        for (int j=0;j<4;j++)
            #pragma unroll
            for (int r=0;r<4;r++) acc[i][j][r]=0.f;

    unsigned abase = (unsigned)__cvta_generic_to_shared(As);
    unsigned bbase = (unsigned)__cvta_generic_to_shared(Bs);

    uint4 ra[4]; uint4 rb[2];
    auto gload = [&](int k0){
        #pragma unroll
        for (int r=0;r<4;r++){
            int idx = tid + r*256; int row = idx>>3, q = idx&7;
            ra[r] = *(const uint4*)&A[(size_t)(m0+row)*K + k0 + q*8];
        }
        #pragma unroll
        for (int r=0;r<2;r++){
            int idx = tid + r*256; int row = idx>>3, q = idx&7;
            rb[r] = *(const uint4*)&Bw[(size_t)(n0+row)*K + k0 + q*8];
        }
    };
    auto sstore = [&](){
        #pragma unroll
        for (int r=0;r<4;r++){
            int idx = tid + r*256; int row = idx>>3, q = idx&7;
            *(uint4*)&As[row*36 + q*4] = ra[r];
        }
        #pragma unroll
        for (int r=0;r<2;r++){
            int idx = tid + r*256; int row = idx>>3, q = idx&7;
            *(uint4*)&Bs[row*36 + q*4] = rb[r];
        }
    };
    auto compute = [&](){
        #pragma unroll
        for (int s=0;s<4;s++){
            unsigned a[2][4], b[4][2];
            #pragma unroll
            for (int i=0;i<2;i++){
                unsigned ad = abase + (((wm + i*16 + (lane&15))*36 + s*8 + (lane>>4)*4)<<2);
                asm volatile("ldmatrix.sync.aligned.m8n8.x4.shared.b16 {%0,%1,%2,%3}, [%4];"
                    : "=r"(a[i][0]),"=r"(a[i][1]),"=r"(a[i][2]),"=r"(a[i][3]) : "r"(ad));
            }
            #pragma unroll
            for (int j=0;j<4;j++){
                unsigned bd = bbase + (((wn + j*8 + (lane&7))*36 + s*8 + ((lane>>3)&1)*4)<<2);
                asm volatile("ldmatrix.sync.aligned.m8n8.x2.shared.b16 {%0,%1}, [%2];"
                    : "=r"(b[j][0]),"=r"(b[j][1]) : "r"(bd));
            }
            #pragma unroll
            for (int i=0;i<2;i++)
                #pragma unroll
                for (int j=0;j<4;j++){
                    asm volatile(
                        "mma.sync.aligned.m16n8k16.row.col.f32.bf16.bf16.f32 "
                        "{%0,%1,%2,%3}, {%4,%5,%6,%7}, {%8,%9}, {%0,%1,%2,%3};"
                        : "+f"(acc[i][j][0]),"+f"(acc[i][j][1]),
                          "+f"(acc[i][j][2]),"+f"(acc[i][j][3])
                        : "r"(a[i][0]),"r"(a[i][1]),"r"(a[i][2]),"r"(a[i][3]),
                          "r"(b[j][0]),"r"(b[j][1]));
                }
        }
    };

    gload(0);
    sstore();
    __syncthreads();
    for (int k0=64; k0<K; k0+=64){
        gload(k0);
        compute();
        __syncthreads();
        sstore();
        __syncthreads();
    }
    compute();

    int rr = lane>>2, c2 = (lane&3)*2;
    #pragma unroll
    for (int i=0;i<2;i++){
        #pragma unroll
        for (int j=0;j<4;j++){
            int m = m0 + wm + i*16 + rr;
            int n = n0 + wn + j*8 + c2;
            float v0 = acc[i][j][0], v1 = acc[i][j][1];
            float v2 = acc[i][j][2], v3 = acc[i][j][3];
            if (resid){
                v0 += resid[(size_t)m*N+n];   v1 += resid[(size_t)m*N+n+1];
                v2 += resid[(size_t)(m+8)*N+n]; v3 += resid[(size_t)(m+8)*N+n+1];
            }
            if (C){
                C[(size_t)m*N+n] = v0;   C[(size_t)m*N+n+1] = v1;
                C[(size_t)(m+8)*N+n] = v2; C[(size_t)(m+8)*N+n+1] = v3;
            }
            if (Cb){
                __nv_bfloat162 p0 = __floats2bfloat162_rn(v0, v1);
                __nv_bfloat162 p1 = __floats2bfloat162_rn(v2, v3);
                *(unsigned*)&Cb[(size_t)m*N+n] = *(unsigned*)&p0;
                *(unsigned*)&Cb[(size_t)(m+8)*N+n] = *(unsigned*)&p1;
            }
        }
    }
}

// ---------------- weight prep: bf16 converts ----------------
__global__ void k_prep(const float* __restrict__ ipw, const float* __restrict__ iplw,
                       const float* __restrict__ opw, const float* __restrict__ xpw,
                       const float* __restrict__ xpwl) {
    int i = blockIdx.x*blockDim.x + threadIdx.x;
    const int n1 = 2*DI*CM, n2 = DI*CM, n3 = CM*DI, n4 = 64*DI;
    if (i < n1) { d_W1b[i] = __float2bfloat16(ipw[i]); return; }
    i -= n1;
    if (i < n2) { d_W2b[i] = __float2bfloat16(iplw[i]); return; }
    i -= n2;
    if (i < n3) { d_W3b[i] = __float2bfloat16(opw[i]); return; }
    i -= n3;
    if (i < n4) { int co=i/DI;
        d_Wtxb[i] = (co<44)? __float2bfloat16(xpw[i]) : __float2bfloat16(0.f); return; }
    i -= n4;
    if (i < n4) { int co=i/DI;
        d_Wtxlb[i] = (co<44)? __float2bfloat16(xpwl[i]) : __float2bfloat16(0.f); return; }
}

// ---------------- fp32 -> bf16 convert (for low) ----------------
__global__ void k_tobf(const float* __restrict__ in, __nv_bfloat16* __restrict__ out, int n4) {
    int i = blockIdx.x*blockDim.x + threadIdx.x;
    if (i >= n4) return;
    float4 v = *(const float4*)&in[i*4];
    __nv_bfloat162 p0 = __floats2bfloat162_rn(v.x, v.y);
    __nv_bfloat162 p1 = __floats2bfloat162_rn(v.z, v.w);
    *(uint2*)&out[i*4] = make_uint2(*(unsigned*)&p0, *(unsigned*)&p1);
}

// ---------------- LayerNorm (warp per pixel) -> bf16 ----------------
__global__ void k_ln(const float* __restrict__ x, const float* __restrict__ g,
                     const float* __restrict__ b) {
    int wid = threadIdx.x>>5, lane = threadIdx.x&31;
    int p = blockIdx.x*8 + wid;
    const float* row = x + (size_t)p*CM;
    float s=0.f, s2=0.f;
    for (int c=lane;c<CM;c+=32){ float v=row[c]; s+=v; s2+=v*v; }
    for (int o=16;o;o>>=1){ s+=__shfl_xor_sync(~0u,s,o); s2+=__shfl_xor_sync(~0u,s2,o); }
    float mean = s/CM, var = s2/CM - mean*mean;
    float rstd = rsqrtf(var + 1e-5f);
    for (int c=lane;c<CM;c+=32)
        d_xnb[(size_t)p*CM+c] = __float2bfloat16((row[c]-mean)*rstd*g[c]+b[c]);
}

// ---------------- depthwise 3x3 conv + bias + SiLU, smem-staged halo ----------------
// Block: d0..d0+31 x one h row, w0..w0+31. Halo tile 3x34x32 staged once.
__global__ __launch_bounds__(256) void k_conv2d_tr(const float* __restrict__ w,
                                                   const float* __restrict__ bias) {
    __shared__ float sxz[3*34*32];
    __shared__ float t[32][33];
    int d0 = blockIdx.x*32, l0 = blockIdx.y*32, b = blockIdx.z;
    int h = l0>>6, w0 = l0&63;
    int tx = threadIdx.x&31, ty = threadIdx.x>>5;
    // stage halo: rows h-1..h+1, cols w0-1..w0+32, 32 d's
    for (int i = threadIdx.x; i < 3*34*32; i += 256){
        int dd = i & 31; int wc = (i>>5) % 34; int row = i / (34*32);
        int hh = h + row - 1, ww = w0 + wc - 1;
        float v = 0.f;
        if ((unsigned)hh < 64u && (unsigned)ww < 64u)
            v = d_xz[((size_t)(b*LL + (hh<<6)+ww))*(2*DI) + d0 + dd];
        sxz[i] = v;
    }
    // weights for this thread's channel
    int d = d0 + tx;
    float wreg[9];
    #pragma unroll
    for (int q=0;q<9;q++) wreg[q] = w[d*9+q];
    float bv = bias[d];
    __syncthreads();
    #pragma unroll
    for (int r=0;r<4;r++){
        int wl = ty + r*8;                       // local w index 0..31
        float acc = bv;
        #pragma unroll
        for (int dy=0;dy<3;dy++)
            #pragma unroll
            for (int dx=0;dx<3;dx++)
                acc = fmaf(wreg[dy*3+dx], sxz[(dy*34 + wl+dx)*32 + tx], acc);
        float v = acc / (1.f + __expf(-acc));
        d_xsb[(size_t)(b*LL + l0+wl)*DI + d] = __float2bfloat16(v);
        t[wl][tx] = v;
    }
    __syncthreads();
    #pragma unroll
    for (int r=0;r<4;r++)
        d_utb[((size_t)b*DI + d0+ty+r*8)*LL + l0+tx] = __float2bfloat16(t[tx][ty+r*8]);
}

// ---------------- combine branches + SimpleGate, 2 pixels per thread ----------------
__global__ void k_combine(const float* __restrict__ w1b, const float* __restrict__ w2b,
                          const float* __restrict__ w1c, const float* __restrict__ w2c) {
    __shared__ float s_w1b[192*16], s_w2b[16*96], s_w1c[192*16], s_w2c[16*96];
    int tid = threadIdx.x;
    for (int i=tid;i<192*16;i+=256){ s_w1b[i]=w1b[i]; s_w1c[i]=w1c[i]; }
    for (int i=tid;i<16*96;i+=256){ s_w2b[i]=w2b[i]; s_w2c[i]=w2c[i]; }
    __syncthreads();
    int gi = blockIdx.x*256 + tid;                 // PX threads total
    int br = gi&1, p0 = (gi>>1)*2;
    const float* w1 = br? s_w1c : s_w1b;
    const float* w2 = br? s_w2c : s_w2b;
    int off = br? 28 : 12;
    float xv[2][16], acc[2][16];
    #pragma unroll
    for (int pp=0;pp<2;pp++){
        const float4* l4 = (const float4*)(d_ldbl + (size_t)(p0+pp)*64 + off);
        #pragma unroll
        for (int q=0;q<4;q++){
            float4 v = l4[q];
            xv[pp][q*4+0]=v.x; xv[pp][q*4+1]=v.y; xv[pp][q*4+2]=v.z; xv[pp][q*4+3]=v.w;
        }
        #pragma unroll
        for (int c=0;c<16;c++) acc[pp][c]=0.f;
    }
    for (int hh=0;hh<96;hh++){
        float y1a=0.f, y2a=0.f, y1b=0.f, y2b=0.f;
        #pragma unroll
        for (int c=0;c<16;c++){
            float wa = w1[hh*16+c], wb = w1[(hh+96)*16+c];
            y1a = fmaf(wa, xv[0][c], y1a);
            y2a = fmaf(wb, xv[0][c], y2a);
            y1b = fmaf(wa, xv[1][c], y1b);
            y2b = fmaf(wb, xv[1][c], y2b);
        }
        float ga = 0.5f*y1a*(1.f+erff(y1a*0.70710678118f))*y2a;
        float gb = 0.5f*y1b*(1.f+erff(y1b*0.70710678118f))*y2b;
        #pragma unroll
        for (int c=0;c<16;c++){
            float wv = w2[c*96+hh];
            acc[0][c] = fmaf(ga, wv, acc[0][c]);
            acc[1][c] = fmaf(gb, wv, acc[1][c]);
        }
    }
    float* outp = br? d_Cs0 : d_Bs0;
    #pragma unroll
    for (int pp=0;pp<2;pp++){
        int p = p0+pp;
        const float* xd = d_xdbl + (size_t)p*64;
        const float4* x4 = (const float4*)(xd + off);
        #pragma unroll
        for (int q=0;q<4;q++){
            float4 v = x4[q];
            float4 o = make_float4(v.x+acc[pp][q*4+0], v.y+acc[pp][q*4+1],
                                   v.z+acc[pp][q*4+2], v.w+acc[pp][q*4+3]);
            *(float4*)&outp[(size_t)p*16 + q*4] = o;
        }
        if (br==0){
            const float* ld = d_ldbl + (size_t)p*64;
            #pragma unroll
            for (int r=0;r<16;r++)
                d_dts0[(size_t)p*16+r] = (r<12)? (xd[r]+ld[r]) : 0.f;
        }
    }
}

// ---------------- residual dilated (dil=2, K=15) depthwise conv1d, float4 ----------------
__global__ void k_dwconv1d(const float* __restrict__ wdt, const float* __restrict__ wB,
                           const float* __restrict__ wC) {
    int idx = blockIdx.x*blockDim.x + threadIdx.x;
    const int per = BD*LL*4;
    int t = idx / per; int rem = idx % per;
    int q = rem & 3; int l = (rem>>2) & (LL-1); int b = rem >> 14;
    const float* in; float* out; const float* w; int nc;
    if (t==0){ in=d_dts0; out=d_dts1; w=wdt; nc=12; }
    else if (t==1){ in=d_Bs0; out=d_Bs1; w=wB; nc=16; }
    else { in=d_Cs0; out=d_Cs1; w=wC; nc=16; }
    size_t base = (size_t)b*LL*16 + q*4;
    int c0 = q*4;
    float4 accv = *(const float4*)&in[base + (size_t)l*16];
    #pragma unroll
    for (int k=0;k<15;k++){
        int ll = l + 2*k - 14;
        if ((unsigned)ll < (unsigned)LL){
            float4 v = *(const float4*)&in[base + (size_t)ll*16];
            float w0 = (c0+0<nc)? w[(c0+0)*15+k] : 0.f;
            float w1 = (c0+1<nc)? w[(c0+1)*15+k] : 0.f;
            float w2 = (c0+2<nc)? w[(c0+2)*15+k] : 0.f;
            float w3 = (c0+3<nc)? w[(c0+3)*15+k] : 0.f;
            accv.x = fmaf(w0, v.x, accv.x);
            accv.y = fmaf(w1, v.y, accv.y);
            accv.z = fmaf(w2, v.z, accv.z);
            accv.w = fmaf(w3, v.w, accv.w);
        }
    }
    *(float4*)&out[base + (size_t)l*16] = accv;
}

// ---------------- selective scan, phase A (fused delta) ----------------
__global__ void k_scanA(const float* __restrict__ A_logs,
                        const float* __restrict__ dtw, const float* __restrict__ dtb) {
    int b = blockIdx.z, chunk = blockIdx.y, ch0 = blockIdx.x*16;
    int tid = threadIdx.x, warp = tid>>5, lane = tid&31, half = lane>>4, n = lane&15;
    int chl = warp*2 + half;
    int d = ch0 + chl;
    float Ac = -expf(A_logs[d*16+n]);
    __shared__ float sB[TT][16], sD[16][TT], sU[16][TT];
    __shared__ float sdts[TT][17];
    __shared__ float sw16[16*12], sb16[16];
    for (int i=tid; i<16*12; i+=256) sw16[i] = dtw[(ch0 + i/12)*12 + (i%12)];
    if (tid < 16) sb16[tid] = dtb[ch0+tid];
    float h = 0.f, ds = 0.f;
    int l0 = chunk*LC;
    for (int t0=0;t0<LC;t0+=TT){
        __syncthreads();
        #pragma unroll
        for (int r=0;r<4;r++){ int j=tid+r*256; int row=j>>4, col=j&15;
            size_t gidx = ((size_t)b*LL + l0+t0+row)*16 + col;
            sB[row][col] = d_Bs1[gidx];
            sdts[row][col] = d_dts1[gidx]; }
        #pragma unroll
        for (int r=0;r<4;r++){ int j=tid+r*256; int ch=j>>6, i=j&63;
            size_t base = ((size_t)b*DI + ch0+ch)*LL + l0+t0;
            sU[ch][i] = __bfloat162float(d_utb[base+i]); }
        __syncthreads();
        #pragma unroll
        for (int r=0;r<4;r++){ int j=tid+r*256; int ch=j>>6, i=j&63;
            float acc = sb16[ch];
            #pragma unroll
            for (int rr=0;rr<12;rr++) acc = fmaf(sdts[i][rr], sw16[ch*12+rr], acc);
            sD[ch][i] = (acc > 20.f)? acc : log1pf(__expf(acc)); }
        __syncthreads();
        #pragma unroll 16
        for (int i=0;i<TT;i++){
            float dly = sD[chl][i], uv = sU[chl][i];
            float a = __expf(dly*Ac);
            h = fmaf(a, h, dly*uv*sB[i][n]);
            ds += dly;
        }
    }
    size_t cb = (size_t)(b*NC+chunk)*DI + d;
    d_hfin[cb*16+n] = h;
    if (n==0) d_dsum[cb] = ds;
}

// ---------------- phase B: stitch chunks ----------------
__global__ void k_scanB(const float* __restrict__ A_logs) {
    int idx = blockIdx.x*blockDim.x + threadIdx.x;
    int n = idx & 15; int d = (idx>>4) % DI; int b = idx/(16*DI);
    float Ac = -expf(A_logs[d*16+n]);
    float H = 0.f;
    for (int c=0;c<NC;c++){
        size_t cb = (size_t)(b*NC+c)*DI + d;
        d_hin[cb*16+n] = H;
        H = __expf(Ac*d_dsum[cb])*H + d_hfin[cb*16+n];
    }
}

// ---------------- phase C: replay (fused delta), emit y (smem reduce) ----------------
__global__ void k_scanC(const float* __restrict__ A_logs, const float* __restrict__ Ds,
                        const float* __restrict__ dtw, const float* __restrict__ dtb) {
    int b = blockIdx.z, chunk = blockIdx.y, ch0 = blockIdx.x*16;
    int tid = threadIdx.x, warp = tid>>5, lane = tid&31, half = lane>>4, n = lane&15;
    int chl = warp*2 + half;
    int d = ch0 + chl;
    float Ac = -expf(A_logs[d*16+n]);
    size_t cb = (size_t)(b*NC+chunk)*DI + d;
    float h = d_hin[cb*16+n];
    __shared__ float sB[TT][16], sC[TT][16], sD[16][TT], sU[16][TT], sY[TT][16];
    __shared__ float sdts[TT][17];
    __shared__ float sP[16][16*17];
    __shared__ float sDs[16];
    __shared__ float sw16[16*12], sb16[16];
    for (int i=tid; i<16*12; i+=256) sw16[i] = dtw[(ch0 + i/12)*12 + (i%12)];
    if (tid < 16) sb16[tid] = dtb[ch0+tid];
    if (n==0) sDs[chl] = Ds[d];
    int l0 = chunk*LC;
    int chl_o = (tid>>4)&15, i2_o = tid&15;
    for (int t0=0;t0<LC;t0+=TT){
        __syncthreads();
        #pragma unroll
        for (int r=0;r<4;r++){ int j=tid+r*256; int row=j>>4, col=j&15;
            size_t gidx = ((size_t)b*LL + l0+t0+row)*16 + col;
            sB[row][col] = d_Bs1[gidx];
            sC[row][col] = d_Cs1[gidx];
            sdts[row][col] = d_dts1[gidx]; }
        #pragma unroll
        for (int r=0;r<4;r++){ int j=tid+r*256; int ch=j>>6, i=j&63;
            size_t base = ((size_t)b*DI + ch0+ch)*LL + l0+t0;
            sU[ch][i] = __bfloat162float(d_utb[base+i]); }
        __syncthreads();
        #pragma unroll
        for (int r=0;r<4;r++){ int j=tid+r*256; int ch=j>>6, i=j&63;
            float acc = sb16[ch];
            #pragma unroll
            for (int rr=0;rr<12;rr++) acc = fmaf(sdts[i][rr], sw16[ch*12+rr], acc);
            sD[ch][i] = (acc > 20.f)? acc : log1pf(__expf(acc)); }
        __syncthreads();
        #pragma unroll
        for (int ii=0; ii<4; ii++){
            #pragma unroll
            for (int i2=0;i2<16;i2++){
                int i = ii*16 + i2;
                float dly = sD[chl][i], uv = sU[chl][i];
                float a = __expf(dly*Ac);
                h = fmaf(a, h, dly*uv*sB[i][n]);
                sP[chl][i2*17+n] = h * sC[i][n];
            }
            __syncthreads();
            {
                float s = 0.f;
                #pragma unroll
                for (int nn=0;nn<16;nn++) s += sP[chl_o][i2_o*17+nn];
                int io = ii*16 + i2_o;
                sY[io][chl_o] = s + sU[chl_o][io]*sDs[chl_o];
            }
            __syncthreads();
        }
        #pragma unroll
        for (int r=0;r<4;r++){ int j=tid+r*256; int row=j>>4, col=j&15;
            d_y[((size_t)b*LL + l0+t0+row)*DI + ch0+col] = sY[row][col]; }
    }
}

// ---------------- out_norm LN * silu(z) -> bf16 (warp per pixel, float4) ----------------
__global__ void k_gate(const float* __restrict__ g, const float* __restrict__ bb) {
    int wid = threadIdx.x>>5, lane = threadIdx.x&31;
    int p = blockIdx.x*8 + wid;
    const float4* row4 = (const float4*)(d_y + (size_t)p*DI);
    const float4* z4   = (const float4*)(d_xz + (size_t)p*(2*DI) + DI);
    const float4* g4   = (const float4*)g;
    const float4* b4   = (const float4*)bb;
    float4 v[3];
    float s=0.f, s2=0.f;
    #pragma unroll
    for (int q=0;q<3;q++){
        v[q] = row4[lane + q*32];
        s  += v[q].x+v[q].y+v[q].z+v[q].w;
        s2 += v[q].x*v[q].x+v[q].y*v[q].y+v[q].z*v[q].z+v[q].w*v[q].w;
    }
    for (int o=16;o;o>>=1){ s+=__shfl_xor_sync(~0u,s,o); s2+=__shfl_xor_sync(~0u,s2,o); }
    float mean = s/DI, var = s2/DI - mean*mean;
    float rstd = rsqrtf(var + 1e-5f);
    __nv_bfloat16* outb = d_gatedb + (size_t)p*DI;
    #pragma unroll
    for (int q=0;q<3;q++){
        int i4 = lane + q*32;
        float4 zz = z4[i4], gg = g4[i4], bv = b4[i4];
        float o0,o1,o2,o3, yn;
        yn = (v[q].x-mean)*rstd*gg.x+bv.x; o0 = yn*(zz.x/(1.f+__expf(-zz.x)));
        yn = (v[q].y-mean)*rstd*gg.y+bv.y; o1 = yn*(zz.y/(1.f+__expf(-zz.y)));
        yn = (v[q].z-mean)*rstd*gg.z+bv.z; o2 = yn*(zz.z/(1.f+__expf(-zz.z)));
        yn = (v[q].w-mean)*rstd*gg.w+bv.w; o3 = yn*(zz.w/(1.f+__expf(-zz.w)));
        __nv_bfloat162 p0 = __floats2bfloat162_rn(o0, o1);
        __nv_bfloat162 p1 = __floats2bfloat162_rn(o2, o3);
        *(uint2*)&outb[i4*4] = make_uint2(*(unsigned*)&p0, *(unsigned*)&p1);
    }
}

// ---------------- launcher ----------------
extern "C" void kernel_launch(void* const* d_in, const int* in_sizes, int n_in,
                              void* d_out, int out_size) {
    const float* x    = (const float*)d_in[0];
    const float* low  = (const float*)d_in[1];
    const float* ln_g = (const float*)d_in[2];
    const float* ln_b = (const float*)d_in[3];
    const float* ipw  = (const float*)d_in[4];
    const float* iplw = (const float*)d_in[5];
    const float* c2w  = (const float*)d_in[6];
    const float* c2b  = (const float*)d_in[7];
    const float* xpw  = (const float*)d_in[8];
    const float* xpwl = (const float*)d_in[9];
    const float* cdtw = (const float*)d_in[10];
    const float* cBw  = (const float*)d_in[11];
    const float* cCw  = (const float*)d_in[12];
    const float* sgbw1= (const float*)d_in[13];
    const float* sgbw2= (const float*)d_in[14];
    const float* sgcw1= (const float*)d_in[15];
    const float* sgcw2= (const float*)d_in[16];
    const float* dtw  = (const float*)d_in[17];
    const float* dtb  = (const float*)d_in[18];
    const float* Alog = (const float*)d_in[19];
    const float* Ds   = (const float*)d_in[20];
    const float* ong  = (const float*)d_in[21];
    const float* onb  = (const float*)d_in[22];
    const float* opw  = (const float*)d_in[23];
    float* out = (float*)d_out;

    void *p_xnb, *p_lowb, *p_xz, *p_lowpb, *p_xsb, *p_xdbl, *p_ldbl, *p_gatedb;
    void *p_W1b, *p_W2b, *p_W3b, *p_Wtxb, *p_Wtxlb;
    cudaGetSymbolAddress(&p_xnb, d_xnb);
    cudaGetSymbolAddress(&p_lowb, d_lowb);
    cudaGetSymbolAddress(&p_xz, d_xz);
    cudaGetSymbolAddress(&p_lowpb, d_lowpb);
    cudaGetSymbolAddress(&p_xsb, d_xsb);
    cudaGetSymbolAddress(&p_xdbl, d_xdbl);
    cudaGetSymbolAddress(&p_ldbl, d_ldbl);
    cudaGetSymbolAddress(&p_gatedb, d_gatedb);
    cudaGetSymbolAddress(&p_W1b, d_W1b);
    cudaGetSymbolAddress(&p_W2b, d_W2b);
    cudaGetSymbolAddress(&p_W3b, d_W3b);
    cudaGetSymbolAddress(&p_Wtxb, d_Wtxb);
    cudaGetSymbolAddress(&p_Wtxlb, d_Wtxlb);

    static cudaStream_t s2 = nullptr;
    static cudaEvent_t evP = nullptr, evLow = nullptr;
    if (!s2){
        cudaStreamCreateWithFlags(&s2, cudaStreamNonBlocking);
        cudaEventCreateWithFlags(&evP,   cudaEventDisableTiming);
        cudaEventCreateWithFlags(&evLow, cudaEventDisableTiming);
    }

    // 1) weight prep
    k_prep<<<(2*DI*CM + DI*CM + CM*DI + 2*64*DI + 255)/256, 256>>>(ipw, iplw, opw, xpw, xpwl);
    cudaEventRecord(evP, 0);
    // 2) pre-LN -> bf16
    k_ln<<<PX/8, 256>>>(x, ln_g, ln_b);
    // 3) convert low -> bf16 (side stream)
    cudaStreamWaitEvent(s2, evP, 0);
    k_tobf<<<(PX*CM/4 + 255)/256, 256, 0, s2>>>(low, (__nv_bfloat16*)p_lowb, PX*CM/4);
    // 4) in_proj (main) <-- profiled
    k_gemm_bf16<<<dim3(768/64, PX/128), 256>>>((const __nv_bfloat16*)p_xnb,
        (const __nv_bfloat16*)p_W1b, (float*)p_xz, nullptr, CM, 2*DI, nullptr);
    // 5) in_proj_low -> bf16 only (side)
    k_gemm_bf16<<<dim3(DI/64, PX/128), 256, 0, s2>>>((const __nv_bfloat16*)p_lowb,
        (const __nv_bfloat16*)p_W2b, nullptr, (__nv_bfloat16*)p_lowpb, CM, DI, nullptr);
    // 6) x_proj low (bf16, side)
    k_gemm_bf16<<<dim3(1, PX/128), 256, 0, s2>>>((const __nv_bfloat16*)p_lowpb,
        (const __nv_bfloat16*)p_Wtxlb, (float*)p_ldbl, nullptr, DI, 64, nullptr);
    cudaEventRecord(evLow, s2);

    // main: conv+silu smem-staged -> bf16 pixel-major + bf16 channel-major
    k_conv2d_tr<<<dim3(DI/32, LL/32, BD), 256>>>(c2w, c2b);
    // x_proj high (bf16)
    k_gemm_bf16<<<dim3(1, PX/128), 256>>>((const __nv_bfloat16*)p_xsb,
        (const __nv_bfloat16*)p_Wtxb, (float*)p_xdbl, nullptr, DI, 64, nullptr);
    cudaStreamWaitEvent(0, evLow, 0);
    k_combine<<<PX/256, 256>>>(sgbw1, sgbw2, sgcw1, sgcw2);
    k_dwconv1d<<<3*BD*LL*4/256, 256>>>(cdtw, cBw, cCw);
    k_scanA<<<dim3(DI/16, NC, BD), 256>>>(Alog, dtw, dtb);
    k_scanB<<<BD*DI*16/256, 256>>>(Alog);
    k_scanC<<<dim3(DI/16, NC, BD), 256>>>(Alog, Ds, dtw, dtb);
    k_gate<<<PX/8, 256>>>(ong, onb);
    // out_proj (+resid x)
    k_gemm_bf16<<<dim3(CM/64, PX/128), 256>>>((const __nv_bfloat16*)p_gatedb,
        (const __nv_bfloat16*)p_W3b, out, nullptr, DI, CM, x);
}

// round 16
// speedup vs baseline: 1.0639x; 1.0639x over previous
#include <cuda_runtime.h>
#include <cuda_bf16.h>
#include <math.h>

#define BD 4
#define LL 4096
#define PX (BD*LL)        // 16384 pixels
#define CM 192
#define DI 384
#define RK 12
#define NS 16
#define NC 8              // scan chunks
#define LC (LL/NC)        // 512
#define TT 64             // scan sub-tile

// ---------------- scratch (device globals; no mallocs allowed) ----------------
__device__ __nv_bfloat16 d_xnb [PX*CM];          // LN out, bf16
__device__ __nv_bfloat16 d_lowb[PX*CM];          // low, bf16
__device__ __nv_bfloat16 d_xzb [(size_t)PX*2*DI]; // in_proj out (xh|z), bf16
__device__ __nv_bfloat16 d_lowpb[(size_t)PX*DI]; // in_proj_low out, bf16
__device__ __nv_bfloat16 d_xsb [(size_t)PX*DI];  // conv out, bf16 pixel-major
__device__ __nv_bfloat16 d_utb [(size_t)BD*DI*LL]; // u channel-major, bf16
__device__ float d_xdbl [PX*64];
__device__ float d_ldbl [PX*64];
__device__ float d_dts0 [PX*16];
__device__ float d_Bs0  [PX*16];
__device__ float d_Cs0  [PX*16];
__device__ float d_dts1 [PX*16];
__device__ float d_Bs1  [PX*16];
__device__ float d_Cs1  [PX*16];
__device__ float d_y    [(size_t)PX*DI];
__device__ __nv_bfloat16 d_gatedb[(size_t)PX*DI];
__device__ __nv_bfloat16 d_W1b [2*DI*CM];        // in_proj   [768][192] bf16
__device__ __nv_bfloat16 d_W2b [DI*CM];          // in_proj_low [384][192]
__device__ __nv_bfloat16 d_W3b [CM*DI];          // out_proj  [192][384]
__device__ __nv_bfloat16 d_Wtxb [64*DI];         // x_proj    [64pad][384]
__device__ __nv_bfloat16 d_Wtxlb[64*DI];         // x_proj_low[64pad][384]
__device__ float d_hfin [BD*NC*DI*NS];
__device__ float d_dsum [BD*NC*DI];
__device__ float d_hin  [BD*NC*DI*NS];

// ---------------- bf16 tensor-core GEMM, BK=64, ldmatrix: C = A·Bw^T ----------------
__global__ __launch_bounds__(256) void k_gemm_bf16(
        const __nv_bfloat16* __restrict__ A, const __nv_bfloat16* __restrict__ Bw,
        float* __restrict__ C, __nv_bfloat16* __restrict__ Cb,
        int K, int N, const float* __restrict__ resid) {
    __shared__ unsigned As[128*36];   // [m][kp], row stride 36 (32+pad4)
    __shared__ unsigned Bs[64*36];
    int m0 = blockIdx.y*128, n0 = blockIdx.x*64;
    int tid = threadIdx.x, lane = tid&31, warp = tid>>5;
    int wm = (warp&3)*32, wn = (warp>>2)*32;
    float acc[2][4][4];
    #pragma unroll
    for (int i=0;i<2;i++)
        #pragma unroll
        for (int j=0;j<4;j++)
            #pragma unroll
            for (int r=0;r<4;r++) acc[i][j][r]=0.f;

    unsigned abase = (unsigned)__cvta_generic_to_shared(As);
    unsigned bbase = (unsigned)__cvta_generic_to_shared(Bs);

    uint4 ra[4]; uint4 rb[2];
    auto gload = [&](int k0){
        #pragma unroll
        for (int r=0;r<4;r++){
            int idx = tid + r*256; int row = idx>>3, q = idx&7;
            ra[r] = *(const uint4*)&A[(size_t)(m0+row)*K + k0 + q*8];
        }
        #pragma unroll
        for (int r=0;r<2;r++){
            int idx = tid + r*256; int row = idx>>3, q = idx&7;
            rb[r] = *(const uint4*)&Bw[(size_t)(n0+row)*K + k0 + q*8];
        }
    };
    auto sstore = [&](){
        #pragma unroll
        for (int r=0;r<4;r++){
            int idx = tid + r*256; int row = idx>>3, q = idx&7;
            *(uint4*)&As[row*36 + q*4] = ra[r];
        }
        #pragma unroll
        for (int r=0;r<2;r++){
            int idx = tid + r*256; int row = idx>>3, q = idx&7;
            *(uint4*)&Bs[row*36 + q*4] = rb[r];
        }
    };
    auto compute = [&](){
        #pragma unroll
        for (int s=0;s<4;s++){
            unsigned a[2][4], b[4][2];
            #pragma unroll
            for (int i=0;i<2;i++){
                unsigned ad = abase + (((wm + i*16 + (lane&15))*36 + s*8 + (lane>>4)*4)<<2);
                asm volatile("ldmatrix.sync.aligned.m8n8.x4.shared.b16 {%0,%1,%2,%3}, [%4];"
                    : "=r"(a[i][0]),"=r"(a[i][1]),"=r"(a[i][2]),"=r"(a[i][3]) : "r"(ad));
            }
            #pragma unroll
            for (int j=0;j<4;j++){
                unsigned bd = bbase + (((wn + j*8 + (lane&7))*36 + s*8 + ((lane>>3)&1)*4)<<2);
                asm volatile("ldmatrix.sync.aligned.m8n8.x2.shared.b16 {%0,%1}, [%2];"
                    : "=r"(b[j][0]),"=r"(b[j][1]) : "r"(bd));
            }
            #pragma unroll
            for (int i=0;i<2;i++)
                #pragma unroll
                for (int j=0;j<4;j++){
                    asm volatile(
                        "mma.sync.aligned.m16n8k16.row.col.f32.bf16.bf16.f32 "
                        "{%0,%1,%2,%3}, {%4,%5,%6,%7}, {%8,%9}, {%0,%1,%2,%3};"
                        : "+f"(acc[i][j][0]),"+f"(acc[i][j][1]),
                          "+f"(acc[i][j][2]),"+f"(acc[i][j][3])
                        : "r"(a[i][0]),"r"(a[i][1]),"r"(a[i][2]),"r"(a[i][3]),
                          "r"(b[j][0]),"r"(b[j][1]));
                }
        }
    };

    gload(0);
    sstore();
    __syncthreads();
    for (int k0=64; k0<K; k0+=64){
        gload(k0);
        compute();
        __syncthreads();
        sstore();
        __syncthreads();
    }
    compute();

    int rr = lane>>2, c2 = (lane&3)*2;
    #pragma unroll
    for (int i=0;i<2;i++){
        #pragma unroll
        for (int j=0;j<4;j++){
            int m = m0 + wm + i*16 + rr;
            int n = n0 + wn + j*8 + c2;
            float v0 = acc[i][j][0], v1 = acc[i][j][1];
            float v2 = acc[i][j][2], v3 = acc[i][j][3];
            if (resid){
                v0 += resid[(size_t)m*N+n];   v1 += resid[(size_t)m*N+n+1];
                v2 += resid[(size_t)(m+8)*N+n]; v3 += resid[(size_t)(m+8)*N+n+1];
            }
            if (C){
                C[(size_t)m*N+n] = v0;   C[(size_t)m*N+n+1] = v1;
                C[(size_t)(m+8)*N+n] = v2; C[(size_t)(m+8)*N+n+1] = v3;
            }
            if (Cb){
                __nv_bfloat162 p0 = __floats2bfloat162_rn(v0, v1);
                __nv_bfloat162 p1 = __floats2bfloat162_rn(v2, v3);
                *(unsigned*)&Cb[(size_t)m*N+n] = *(unsigned*)&p0;
                *(unsigned*)&Cb[(size_t)(m+8)*N+n] = *(unsigned*)&p1;
            }
        }
    }
}

// ---------------- weight prep: bf16 converts ----------------
__global__ void k_prep(const float* __restrict__ ipw, const float* __restrict__ iplw,
                       const float* __restrict__ opw, const float* __restrict__ xpw,
                       const float* __restrict__ xpwl) {
    int i = blockIdx.x*blockDim.x + threadIdx.x;
    const int n1 = 2*DI*CM, n2 = DI*CM, n3 = CM*DI, n4 = 64*DI;
    if (i < n1) { d_W1b[i] = __float2bfloat16(ipw[i]); return; }
    i -= n1;
    if (i < n2) { d_W2b[i] = __float2bfloat16(iplw[i]); return; }
    i -= n2;
    if (i < n3) { d_W3b[i] = __float2bfloat16(opw[i]); return; }
    i -= n3;
    if (i < n4) { int co=i/DI;
        d_Wtxb[i] = (co<44)? __float2bfloat16(xpw[i]) : __float2bfloat16(0.f); return; }
    i -= n4;
    if (i < n4) { int co=i/DI;
        d_Wtxlb[i] = (co<44)? __float2bfloat16(xpwl[i]) : __float2bfloat16(0.f); return; }
}

// ---------------- fp32 -> bf16 convert (for low) ----------------
__global__ void k_tobf(const float* __restrict__ in, __nv_bfloat16* __restrict__ out, int n4) {
    int i = blockIdx.x*blockDim.x + threadIdx.x;
    if (i >= n4) return;
    float4 v = *(const float4*)&in[i*4];
    __nv_bfloat162 p0 = __floats2bfloat162_rn(v.x, v.y);
    __nv_bfloat162 p1 = __floats2bfloat162_rn(v.z, v.w);
    *(uint2*)&out[i*4] = make_uint2(*(unsigned*)&p0, *(unsigned*)&p1);
}

// ---------------- LayerNorm (warp per pixel) -> bf16 ----------------
__global__ void k_ln(const float* __restrict__ x, const float* __restrict__ g,
                     const float* __restrict__ b) {
    int wid = threadIdx.x>>5, lane = threadIdx.x&31;
    int p = blockIdx.x*8 + wid;
    const float* row = x + (size_t)p*CM;
    float s=0.f, s2=0.f;
    for (int c=lane;c<CM;c+=32){ float v=row[c]; s+=v; s2+=v*v; }
    for (int o=16;o;o>>=1){ s+=__shfl_xor_sync(~0u,s,o); s2+=__shfl_xor_sync(~0u,s2,o); }
    float mean = s/CM, var = s2/CM - mean*mean;
    float rstd = rsqrtf(var + 1e-5f);
    for (int c=lane;c<CM;c+=32)
        d_xnb[(size_t)p*CM+c] = __float2bfloat16((row[c]-mean)*rstd*g[c]+b[c]);
}

// ---------------- depthwise 3x3 conv + bias + SiLU (bf16 in/out, R14 structure) ----------------
__global__ __launch_bounds__(256) void k_conv2d_tr(const float* __restrict__ w,
                                                   const float* __restrict__ bias) {
    __shared__ float t[32][33];
    int d0 = blockIdx.x*32, l0 = blockIdx.y*32, b = blockIdx.z;
    int tx = threadIdx.x&31, ty = threadIdx.x>>5;
    #pragma unroll
    for (int r=0;r<4;r++){
        int l = l0 + ty + r*8;
        int h = l>>6, wc = l&63;
        int d = d0 + tx;
        float acc = bias[d];
        #pragma unroll
        for (int dy=0;dy<3;dy++){
            int hh = h+dy-1; if ((unsigned)hh >= 64u) continue;
            #pragma unroll
            for (int dx=0;dx<3;dx++){
                int ww = wc+dx-1; if ((unsigned)ww >= 64u) continue;
                acc = fmaf(w[d*9+dy*3+dx],
                           __bfloat162float(d_xzb[((size_t)(b*LL + (hh<<6)+ww))*(2*DI) + d]), acc);
            }
        }
        float v = acc / (1.f + __expf(-acc));
        d_xsb[(size_t)(b*LL+l)*DI + d] = __float2bfloat16(v);
        t[l-l0][tx] = v;
    }
    __syncthreads();
    #pragma unroll
    for (int r=0;r<4;r++)
        d_utb[((size_t)b*DI + d0+ty+r*8)*LL + l0+tx] = __float2bfloat16(t[tx][ty+r*8]);
}

// ---------------- combine branches + SimpleGate on low B/C (R12 form) ----------------
__global__ void k_combine(const float* __restrict__ w1b, const float* __restrict__ w2b,
                          const float* __restrict__ w1c, const float* __restrict__ w2c) {
    __shared__ float s_w1b[192*16], s_w2b[16*96], s_w1c[192*16], s_w2c[16*96];
    int tid = threadIdx.x;
    for (int i=tid;i<192*16;i+=256){ s_w1b[i]=w1b[i]; s_w1c[i]=w1c[i]; }
    for (int i=tid;i<16*96;i+=256){ s_w2b[i]=w2b[i]; s_w2c[i]=w2c[i]; }
    __syncthreads();
    int gi = blockIdx.x*256 + tid;
    int p = gi>>1, br = gi&1;
    const float* xd = d_xdbl + (size_t)p*64;
    const float* ld = d_ldbl + (size_t)p*64;
    const float* w1 = br? s_w1c : s_w1b;
    const float* w2 = br? s_w2c : s_w2b;
    int off = br? 28 : 12;
    float xv[16], acc[16];
    {
        const float4* l4 = (const float4*)(ld + off);
        #pragma unroll
        for (int q=0;q<4;q++){
            float4 v = l4[q];
            xv[q*4+0]=v.x; xv[q*4+1]=v.y; xv[q*4+2]=v.z; xv[q*4+3]=v.w;
        }
    }
    #pragma unroll
    for (int c=0;c<16;c++) acc[c]=0.f;
    for (int hh=0;hh<96;hh++){
        float y1=0.f, y2=0.f;
        #pragma unroll
        for (int c=0;c<16;c++){
            y1 = fmaf(w1[hh*16+c], xv[c], y1);
            y2 = fmaf(w1[(hh+96)*16+c], xv[c], y2);
        }
        float g = 0.5f*y1*(1.f+erff(y1*0.70710678118f))*y2;
        #pragma unroll
        for (int c=0;c<16;c++) acc[c] = fmaf(g, w2[c*96+hh], acc[c]);
    }
    float* outp = br? d_Cs0 : d_Bs0;
    const float4* x4 = (const float4*)(xd + off);
    #pragma unroll
    for (int q=0;q<4;q++){
        float4 v = x4[q];
        float4 o = make_float4(v.x+acc[q*4+0], v.y+acc[q*4+1],
                               v.z+acc[q*4+2], v.w+acc[q*4+3]);
        *(float4*)&outp[(size_t)p*16 + q*4] = o;
    }
    if (br==0){
        #pragma unroll
        for (int r=0;r<16;r++)
            d_dts0[(size_t)p*16+r] = (r<12)? (xd[r]+ld[r]) : 0.f;
    }
}

// ---------------- residual dilated (dil=2, K=15) depthwise conv1d, float4 ----------------
__global__ void k_dwconv1d(const float* __restrict__ wdt, const float* __restrict__ wB,
                           const float* __restrict__ wC) {
    int idx = blockIdx.x*blockDim.x + threadIdx.x;
    const int per = BD*LL*4;
    int t = idx / per; int rem = idx % per;
    int q = rem & 3; int l = (rem>>2) & (LL-1); int b = rem >> 14;
    const float* in; float* out; const float* w; int nc;
    if (t==0){ in=d_dts0; out=d_dts1; w=wdt; nc=12; }
    else if (t==1){ in=d_Bs0; out=d_Bs1; w=wB; nc=16; }
    else { in=d_Cs0; out=d_Cs1; w=wC; nc=16; }
    size_t base = (size_t)b*LL*16 + q*4;
    int c0 = q*4;
    float4 accv = *(const float4*)&in[base + (size_t)l*16];
    #pragma unroll
    for (int k=0;k<15;k++){
        int ll = l + 2*k - 14;
        if ((unsigned)ll < (unsigned)LL){
            float4 v = *(const float4*)&in[base + (size_t)ll*16];
            float w0 = (c0+0<nc)? w[(c0+0)*15+k] : 0.f;
            float w1 = (c0+1<nc)? w[(c0+1)*15+k] : 0.f;
            float w2 = (c0+2<nc)? w[(c0+2)*15+k] : 0.f;
            float w3 = (c0+3<nc)? w[(c0+3)*15+k] : 0.f;
            accv.x = fmaf(w0, v.x, accv.x);
            accv.y = fmaf(w1, v.y, accv.y);
            accv.z = fmaf(w2, v.z, accv.z);
            accv.w = fmaf(w3, v.w, accv.w);
        }
    }
    *(float4*)&out[base + (size_t)l*16] = accv;
}

// ---------------- selective scan, phase A (fused delta) ----------------
__global__ void k_scanA(const float* __restrict__ A_logs,
                        const float* __restrict__ dtw, const float* __restrict__ dtb) {
    int b = blockIdx.z, chunk = blockIdx.y, ch0 = blockIdx.x*16;
    int tid = threadIdx.x, warp = tid>>5, lane = tid&31, half = lane>>4, n = lane&15;
    int chl = warp*2 + half;
    int d = ch0 + chl;
    float Ac = -expf(A_logs[d*16+n]);
    __shared__ float sB[TT][16], sD[16][TT], sU[16][TT];
    __shared__ float sdts[TT][17];
    __shared__ float sw16[16*12], sb16[16];
    for (int i=tid; i<16*12; i+=256) sw16[i] = dtw[(ch0 + i/12)*12 + (i%12)];
    if (tid < 16) sb16[tid] = dtb[ch0+tid];
    float h = 0.f, ds = 0.f;
    int l0 = chunk*LC;
    for (int t0=0;t0<LC;t0+=TT){
        __syncthreads();
        #pragma unroll
        for (int r=0;r<4;r++){ int j=tid+r*256; int row=j>>4, col=j&15;
            size_t gidx = ((size_t)b*LL + l0+t0+row)*16 + col;
            sB[row][col] = d_Bs1[gidx];
            sdts[row][col] = d_dts1[gidx]; }
        #pragma unroll
        for (int r=0;r<4;r++){ int j=tid+r*256; int ch=j>>6, i=j&63;
            size_t base = ((size_t)b*DI + ch0+ch)*LL + l0+t0;
            sU[ch][i] = __bfloat162float(d_utb[base+i]); }
        __syncthreads();
        #pragma unroll
        for (int r=0;r<4;r++){ int j=tid+r*256; int ch=j>>6, i=j&63;
            float acc = sb16[ch];
            #pragma unroll
            for (int rr=0;rr<12;rr++) acc = fmaf(sdts[i][rr], sw16[ch*12+rr], acc);
            sD[ch][i] = (acc > 20.f)? acc : log1pf(__expf(acc)); }
        __syncthreads();
        #pragma unroll 16
        for (int i=0;i<TT;i++){
            float dly = sD[chl][i], uv = sU[chl][i];
            float a = __expf(dly*Ac);
            h = fmaf(a, h, dly*uv*sB[i][n]);
            ds += dly;
        }
    }
    size_t cb = (size_t)(b*NC+chunk)*DI + d;
    d_hfin[cb*16+n] = h;
    if (n==0) d_dsum[cb] = ds;
}

// ---------------- phase B: stitch chunks ----------------
__global__ void k_scanB(const float* __restrict__ A_logs) {
    int idx = blockIdx.x*blockDim.x + threadIdx.x;
    int n = idx & 15; int d = (idx>>4) % DI; int b = idx/(16*DI);
    float Ac = -expf(A_logs[d*16+n]);
    float H = 0.f;
    for (int c=0;c<NC;c++){
        size_t cb = (size_t)(b*NC+c)*DI + d;
        d_hin[cb*16+n] = H;
        H = __expf(Ac*d_dsum[cb])*H + d_hfin[cb*16+n];
    }
}

// ---------------- phase C: replay (fused delta), emit y (smem reduce) ----------------
__global__ void k_scanC(const float* __restrict__ A_logs, const float* __restrict__ Ds,
                        const float* __restrict__ dtw, const float* __restrict__ dtb) {
    int b = blockIdx.z, chunk = blockIdx.y, ch0 = blockIdx.x*16;
    int tid = threadIdx.x, warp = tid>>5, lane = tid&31, half = lane>>4, n = lane&15;
    int chl = warp*2 + half;
    int d = ch0 + chl;
    float Ac = -expf(A_logs[d*16+n]);
    size_t cb = (size_t)(b*NC+chunk)*DI + d;
    float h = d_hin[cb*16+n];
    __shared__ float sB[TT][16], sC[TT][16], sD[16][TT], sU[16][TT], sY[TT][16];
    __shared__ float sdts[TT][17];
    __shared__ float sP[16][16*17];
    __shared__ float sDs[16];
    __shared__ float sw16[16*12], sb16[16];
    for (int i=tid; i<16*12; i+=256) sw16[i] = dtw[(ch0 + i/12)*12 + (i%12)];
    if (tid < 16) sb16[tid] = dtb[ch0+tid];
    if (n==0) sDs[chl] = Ds[d];
    int l0 = chunk*LC;
    int chl_o = (tid>>4)&15, i2_o = tid&15;
    for (int t0=0;t0<LC;t0+=TT){
        __syncthreads();
        #pragma unroll
        for (int r=0;r<4;r++){ int j=tid+r*256; int row=j>>4, col=j&15;
            size_t gidx = ((size_t)b*LL + l0+t0+row)*16 + col;
            sB[row][col] = d_Bs1[gidx];
            sC[row][col] = d_Cs1[gidx];
            sdts[row][col] = d_dts1[gidx]; }
        #pragma unroll
        for (int r=0;r<4;r++){ int j=tid+r*256; int ch=j>>6, i=j&63;
            size_t base = ((size_t)b*DI + ch0+ch)*LL + l0+t0;
            sU[ch][i] = __bfloat162float(d_utb[base+i]); }
        __syncthreads();
        #pragma unroll
        for (int r=0;r<4;r++){ int j=tid+r*256; int ch=j>>6, i=j&63;
            float acc = sb16[ch];
            #pragma unroll
            for (int rr=0;rr<12;rr++) acc = fmaf(sdts[i][rr], sw16[ch*12+rr], acc);
            sD[ch][i] = (acc > 20.f)? acc : log1pf(__expf(acc)); }
        __syncthreads();
        #pragma unroll
        for (int ii=0; ii<4; ii++){
            #pragma unroll
            for (int i2=0;i2<16;i2++){
                int i = ii*16 + i2;
                float dly = sD[chl][i], uv = sU[chl][i];
                float a = __expf(dly*Ac);
                h = fmaf(a, h, dly*uv*sB[i][n]);
                sP[chl][i2*17+n] = h * sC[i][n];
            }
            __syncthreads();
            {
                float s = 0.f;
                #pragma unroll
                for (int nn=0;nn<16;nn++) s += sP[chl_o][i2_o*17+nn];
                int io = ii*16 + i2_o;
                sY[io][chl_o] = s + sU[chl_o][io]*sDs[chl_o];
            }
            __syncthreads();
        }
        #pragma unroll
        for (int r=0;r<4;r++){ int j=tid+r*256; int row=j>>4, col=j&15;
            d_y[((size_t)b*LL + l0+t0+row)*DI + ch0+col] = sY[row][col]; }
    }
}

// ---------------- out_norm LN * silu(z) -> bf16 (warp per pixel; z from bf16) ----------------
__global__ void k_gate(const float* __restrict__ g, const float* __restrict__ bb) {
    int wid = threadIdx.x>>5, lane = threadIdx.x&31;
    int p = blockIdx.x*8 + wid;
    const float4* row4 = (const float4*)(d_y + (size_t)p*DI);
    const __nv_bfloat16* zrow = d_xzb + (size_t)p*(2*DI) + DI;
    const float4* g4   = (const float4*)g;
    const float4* b4   = (const float4*)bb;
    float4 v[3];
    float s=0.f, s2=0.f;
    #pragma unroll
    for (int q=0;q<3;q++){
        v[q] = row4[lane + q*32];
        s  += v[q].x+v[q].y+v[q].z+v[q].w;
        s2 += v[q].x*v[q].x+v[q].y*v[q].y+v[q].z*v[q].z+v[q].w*v[q].w;
    }
    for (int o=16;o;o>>=1){ s+=__shfl_xor_sync(~0u,s,o); s2+=__shfl_xor_sync(~0u,s2,o); }
    float mean = s/DI, var = s2/DI - mean*mean;
    float rstd = rsqrtf(var + 1e-5f);
    __nv_bfloat16* outb = d_gatedb + (size_t)p*DI;
    #pragma unroll
    for (int q=0;q<3;q++){
        int i4 = lane + q*32;
        uint2 zb = *(const uint2*)&zrow[i4*4];
        __nv_bfloat162 zp0 = *(__nv_bfloat162*)&zb.x;
        __nv_bfloat162 zp1 = *(__nv_bfloat162*)&zb.y;
        float z0 = __bfloat162float(__low2bfloat16(zp0));
        float z1 = __bfloat162float(__high2bfloat16(zp0));
        float z2 = __bfloat162float(__low2bfloat16(zp1));
        float z3 = __bfloat162float(__high2bfloat16(zp1));
        float4 gg = g4[i4], bv = b4[i4];
        float o0,o1,o2,o3, yn;
        yn = (v[q].x-mean)*rstd*gg.x+bv.x; o0 = yn*(z0/(1.f+__expf(-z0)));
        yn = (v[q].y-mean)*rstd*gg.y+bv.y; o1 = yn*(z1/(1.f+__expf(-z1)));
        yn = (v[q].z-mean)*rstd*gg.z+bv.z; o2 = yn*(z2/(1.f+__expf(-z2)));
        yn = (v[q].w-mean)*rstd*gg.w+bv.w; o3 = yn*(z3/(1.f+__expf(-z3)));
        __nv_bfloat162 p0 = __floats2bfloat162_rn(o0, o1);
        __nv_bfloat162 p1 = __floats2bfloat162_rn(o2, o3);
        *(uint2*)&outb[i4*4] = make_uint2(*(unsigned*)&p0, *(unsigned*)&p1);
    }
}

// ---------------- launcher ----------------
extern "C" void kernel_launch(void* const* d_in, const int* in_sizes, int n_in,
                              void* d_out, int out_size) {
    const float* x    = (const float*)d_in[0];
    const float* low  = (const float*)d_in[1];
    const float* ln_g = (const float*)d_in[2];
    const float* ln_b = (const float*)d_in[3];
    const float* ipw  = (const float*)d_in[4];
    const float* iplw = (const float*)d_in[5];
    const float* c2w  = (const float*)d_in[6];
    const float* c2b  = (const float*)d_in[7];
    const float* xpw  = (const float*)d_in[8];
    const float* xpwl = (const float*)d_in[9];
    const float* cdtw = (const float*)d_in[10];
    const float* cBw  = (const float*)d_in[11];
    const float* cCw  = (const float*)d_in[12];
    const float* sgbw1= (const float*)d_in[13];
    const float* sgbw2= (const float*)d_in[14];
    const float* sgcw1= (const float*)d_in[15];
    const float* sgcw2= (const float*)d_in[16];
    const float* dtw  = (const float*)d_in[17];
    const float* dtb  = (const float*)d_in[18];
    const float* Alog = (const float*)d_in[19];
    const float* Ds   = (const float*)d_in[20];
    const float* ong  = (const float*)d_in[21];
    const float* onb  = (const float*)d_in[22];
    const float* opw  = (const float*)d_in[23];
    float* out = (float*)d_out;

    void *p_xnb, *p_lowb, *p_xzb, *p_lowpb, *p_xsb, *p_xdbl, *p_ldbl, *p_gatedb;
    void *p_W1b, *p_W2b, *p_W3b, *p_Wtxb, *p_Wtxlb;
    cudaGetSymbolAddress(&p_xnb, d_xnb);
    cudaGetSymbolAddress(&p_lowb, d_lowb);
    cudaGetSymbolAddress(&p_xzb, d_xzb);
    cudaGetSymbolAddress(&p_lowpb, d_lowpb);
    cudaGetSymbolAddress(&p_xsb, d_xsb);
    cudaGetSymbolAddress(&p_xdbl, d_xdbl);
    cudaGetSymbolAddress(&p_ldbl, d_ldbl);
    cudaGetSymbolAddress(&p_gatedb, d_gatedb);
    cudaGetSymbolAddress(&p_W1b, d_W1b);
    cudaGetSymbolAddress(&p_W2b, d_W2b);
    cudaGetSymbolAddress(&p_W3b, d_W3b);
    cudaGetSymbolAddress(&p_Wtxb, d_Wtxb);
    cudaGetSymbolAddress(&p_Wtxlb, d_Wtxlb);

    static cudaStream_t s2 = nullptr;
    static cudaEvent_t evP = nullptr, evLow = nullptr;
    if (!s2){
        cudaStreamCreateWithFlags(&s2, cudaStreamNonBlocking);
        cudaEventCreateWithFlags(&evP,   cudaEventDisableTiming);
        cudaEventCreateWithFlags(&evLow, cudaEventDisableTiming);
    }

    // 1) weight prep
    k_prep<<<(2*DI*CM + DI*CM + CM*DI + 2*64*DI + 255)/256, 256>>>(ipw, iplw, opw, xpw, xpwl);
    cudaEventRecord(evP, 0);
    // 2) pre-LN -> bf16
    k_ln<<<PX/8, 256>>>(x, ln_g, ln_b);
    // 3) convert low -> bf16 (side stream)
    cudaStreamWaitEvent(s2, evP, 0);
    k_tobf<<<(PX*CM/4 + 255)/256, 256, 0, s2>>>(low, (__nv_bfloat16*)p_lowb, PX*CM/4);
    // 4) in_proj -> bf16 xz (main) <-- profiled
    k_gemm_bf16<<<dim3(768/64, PX/128), 256>>>((const __nv_bfloat16*)p_xnb,
        (const __nv_bfloat16*)p_W1b, nullptr, (__nv_bfloat16*)p_xzb, CM, 2*DI, nullptr);
    // 5) in_proj_low -> bf16 only (side)
    k_gemm_bf16<<<dim3(DI/64, PX/128), 256, 0, s2>>>((const __nv_bfloat16*)p_lowb,
        (const __nv_bfloat16*)p_W2b, nullptr, (__nv_bfloat16*)p_lowpb, CM, DI, nullptr);
    // 6) x_proj low (bf16, side)
    k_gemm_bf16<<<dim3(1, PX/128), 256, 0, s2>>>((const __nv_bfloat16*)p_lowpb,
        (const __nv_bfloat16*)p_Wtxlb, (float*)p_ldbl, nullptr, DI, 64, nullptr);
    cudaEventRecord(evLow, s2);

    // main: conv+silu -> bf16 pixel-major + bf16 channel-major
    k_conv2d_tr<<<dim3(DI/32, LL/32, BD), 256>>>(c2w, c2b);
    // x_proj high (bf16)
    k_gemm_bf16<<<dim3(1, PX/128), 256>>>((const __nv_bfloat16*)p_xsb,
        (const __nv_bfloat16*)p_Wtxb, (float*)p_xdbl, nullptr, DI, 64, nullptr);
    cudaStreamWaitEvent(0, evLow, 0);
    k_combine<<<2*PX/256, 256>>>(sgbw1, sgbw2, sgcw1, sgcw2);
    k_dwconv1d<<<3*BD*LL*4/256, 256>>>(cdtw, cBw, cCw);
    k_scanA<<<dim3(DI/16, NC, BD), 256>>>(Alog, dtw, dtb);
    k_scanB<<<BD*DI*16/256, 256>>>(Alog);
    k_scanC<<<dim3(DI/16, NC, BD), 256>>>(Alog, Ds, dtw, dtb);
    k_gate<<<PX/8, 256>>>(ong, onb);
    // out_proj (+resid x)
    k_gemm_bf16<<<dim3(CM/64, PX/128), 256>>>((const __nv_bfloat16*)p_gatedb,
        (const __nv_bfloat16*)p_W3b, out, nullptr, DI, CM, x);
}

// round 17
// speedup vs baseline: 1.1066x; 1.0401x over previous
#include <cuda_runtime.h>
#include <cuda_bf16.h>
#include <math.h>

#define BD 4
#define LL 4096
#define PX (BD*LL)        // 16384 pixels
#define CM 192
#define DI 384
#define RK 12
#define NS 16
#define NC 16             // scan chunks
#define LC (LL/NC)        // 256
#define TT 64             // scan sub-tile

// ---------------- scratch (device globals; no mallocs allowed) ----------------
__device__ __nv_bfloat16 d_xnb [PX*CM];          // LN out, bf16
__device__ __nv_bfloat16 d_lowb[PX*CM];          // low, bf16
__device__ __nv_bfloat16 d_xzb [(size_t)PX*2*DI]; // in_proj out (xh|z), bf16
__device__ __nv_bfloat16 d_lowpb[(size_t)PX*DI]; // in_proj_low out, bf16
__device__ __nv_bfloat16 d_xsb [(size_t)PX*DI];  // conv out, bf16 pixel-major
__device__ __nv_bfloat16 d_utb [(size_t)BD*DI*LL]; // u channel-major, bf16
__device__ float d_xdbl [PX*64];
__device__ float d_ldbl [PX*64];
__device__ float d_dts0 [PX*16];
__device__ float d_Bs0  [PX*16];
__device__ float d_Cs0  [PX*16];
__device__ float d_dts1 [PX*16];
__device__ float d_Bs1  [PX*16];
__device__ float d_Cs1  [PX*16];
__device__ __nv_bfloat16 d_yb [(size_t)PX*DI];   // scan out, bf16
__device__ __nv_bfloat16 d_gatedb[(size_t)PX*DI];
__device__ __nv_bfloat16 d_W1b [2*DI*CM];        // in_proj   [768][192] bf16
__device__ __nv_bfloat16 d_W2b [DI*CM];          // in_proj_low [384][192]
__device__ __nv_bfloat16 d_W3b [CM*DI];          // out_proj  [192][384]
__device__ __nv_bfloat16 d_Wtxb [64*DI];         // x_proj    [64pad][384]
__device__ __nv_bfloat16 d_Wtxlb[64*DI];         // x_proj_low[64pad][384]
__device__ float d_hfin [BD*NC*DI*NS];
__device__ float d_dsum [BD*NC*DI];
__device__ float d_hin  [BD*NC*DI*NS];

// ---------------- bf16 tensor-core GEMM, BK=64, ldmatrix: C = A·Bw^T ----------------
__global__ __launch_bounds__(256) void k_gemm_bf16(
        const __nv_bfloat16* __restrict__ A, const __nv_bfloat16* __restrict__ Bw,
        float* __restrict__ C, __nv_bfloat16* __restrict__ Cb,
        int K, int N, const float* __restrict__ resid) {
    __shared__ unsigned As[128*36];   // [m][kp], row stride 36 (32+pad4)
    __shared__ unsigned Bs[64*36];
    int m0 = blockIdx.y*128, n0 = blockIdx.x*64;
    int tid = threadIdx.x, lane = tid&31, warp = tid>>5;
    int wm = (warp&3)*32, wn = (warp>>2)*32;
    float acc[2][4][4];
    #pragma unroll
    for (int i=0;i<2;i++)
        #pragma unroll
        for (int j=0;j<4;j++)
            #pragma unroll
            for (int r=0;r<4;r++) acc[i][j][r]=0.f;

    unsigned abase = (unsigned)__cvta_generic_to_shared(As);
    unsigned bbase = (unsigned)__cvta_generic_to_shared(Bs);

    uint4 ra[4]; uint4 rb[2];
    auto gload = [&](int k0){
        #pragma unroll
        for (int r=0;r<4;r++){
            int idx = tid + r*256; int row = idx>>3, q = idx&7;
            ra[r] = *(const uint4*)&A[(size_t)(m0+row)*K + k0 + q*8];
        }
        #pragma unroll
        for (int r=0;r<2;r++){
            int idx = tid + r*256; int row = idx>>3, q = idx&7;
            rb[r] = *(const uint4*)&Bw[(size_t)(n0+row)*K + k0 + q*8];
        }
    };
    auto sstore = [&](){
        #pragma unroll
        for (int r=0;r<4;r++){
            int idx = tid + r*256; int row = idx>>3, q = idx&7;
            *(uint4*)&As[row*36 + q*4] = ra[r];
        }
        #pragma unroll
        for (int r=0;r<2;r++){
            int idx = tid + r*256; int row = idx>>3, q = idx&7;
            *(uint4*)&Bs[row*36 + q*4] = rb[r];
        }
    };
    auto compute = [&](){
        #pragma unroll
        for (int s=0;s<4;s++){
            unsigned a[2][4], b[4][2];
            #pragma unroll
            for (int i=0;i<2;i++){
                unsigned ad = abase + (((wm + i*16 + (lane&15))*36 + s*8 + (lane>>4)*4)<<2);
                asm volatile("ldmatrix.sync.aligned.m8n8.x4.shared.b16 {%0,%1,%2,%3}, [%4];"
                    : "=r"(a[i][0]),"=r"(a[i][1]),"=r"(a[i][2]),"=r"(a[i][3]) : "r"(ad));
            }
            #pragma unroll
            for (int j=0;j<4;j++){
                unsigned bd = bbase + (((wn + j*8 + (lane&7))*36 + s*8 + ((lane>>3)&1)*4)<<2);
                asm volatile("ldmatrix.sync.aligned.m8n8.x2.shared.b16 {%0,%1}, [%2];"
                    : "=r"(b[j][0]),"=r"(b[j][1]) : "r"(bd));
            }
            #pragma unroll
            for (int i=0;i<2;i++)
                #pragma unroll
                for (int j=0;j<4;j++){
                    asm volatile(
                        "mma.sync.aligned.m16n8k16.row.col.f32.bf16.bf16.f32 "
                        "{%0,%1,%2,%3}, {%4,%5,%6,%7}, {%8,%9}, {%0,%1,%2,%3};"
                        : "+f"(acc[i][j][0]),"+f"(acc[i][j][1]),
                          "+f"(acc[i][j][2]),"+f"(acc[i][j][3])
                        : "r"(a[i][0]),"r"(a[i][1]),"r"(a[i][2]),"r"(a[i][3]),
                          "r"(b[j][0]),"r"(b[j][1]));
                }
        }
    };

    gload(0);
    sstore();
    __syncthreads();
    for (int k0=64; k0<K; k0+=64){
        gload(k0);
        compute();
        __syncthreads();
        sstore();
        __syncthreads();
    }
    compute();

    int rr = lane>>2, c2 = (lane&3)*2;
    #pragma unroll
    for (int i=0;i<2;i++){
        #pragma unroll
        for (int j=0;j<4;j++){
            int m = m0 + wm + i*16 + rr;
            int n = n0 + wn + j*8 + c2;
            float v0 = acc[i][j][0], v1 = acc[i][j][1];
            float v2 = acc[i][j][2], v3 = acc[i][j][3];
            if (resid){
                v0 += resid[(size_t)m*N+n];   v1 += resid[(size_t)m*N+n+1];
                v2 += resid[(size_t)(m+8)*N+n]; v3 += resid[(size_t)(m+8)*N+n+1];
            }
            if (C){
                C[(size_t)m*N+n] = v0;   C[(size_t)m*N+n+1] = v1;
                C[(size_t)(m+8)*N+n] = v2; C[(size_t)(m+8)*N+n+1] = v3;
            }
            if (Cb){
                __nv_bfloat162 p0 = __floats2bfloat162_rn(v0, v1);
                __nv_bfloat162 p1 = __floats2bfloat162_rn(v2, v3);
                *(unsigned*)&Cb[(size_t)m*N+n] = *(unsigned*)&p0;
                *(unsigned*)&Cb[(size_t)(m+8)*N+n] = *(unsigned*)&p1;
            }
        }
    }
}

// ---------------- weight prep: bf16 converts ----------------
__global__ void k_prep(const float* __restrict__ ipw, const float* __restrict__ iplw,
                       const float* __restrict__ opw, const float* __restrict__ xpw,
                       const float* __restrict__ xpwl) {
    int i = blockIdx.x*blockDim.x + threadIdx.x;
    const int n1 = 2*DI*CM, n2 = DI*CM, n3 = CM*DI, n4 = 64*DI;
    if (i < n1) { d_W1b[i] = __float2bfloat16(ipw[i]); return; }
    i -= n1;
    if (i < n2) { d_W2b[i] = __float2bfloat16(iplw[i]); return; }
    i -= n2;
    if (i < n3) { d_W3b[i] = __float2bfloat16(opw[i]); return; }
    i -= n3;
    if (i < n4) { int co=i/DI;
        d_Wtxb[i] = (co<44)? __float2bfloat16(xpw[i]) : __float2bfloat16(0.f); return; }
    i -= n4;
    if (i < n4) { int co=i/DI;
        d_Wtxlb[i] = (co<44)? __float2bfloat16(xpwl[i]) : __float2bfloat16(0.f); return; }
}

// ---------------- fp32 -> bf16 convert (for low) ----------------
__global__ void k_tobf(const float* __restrict__ in, __nv_bfloat16* __restrict__ out, int n4) {
    int i = blockIdx.x*blockDim.x + threadIdx.x;
    if (i >= n4) return;
    float4 v = *(const float4*)&in[i*4];
    __nv_bfloat162 p0 = __floats2bfloat162_rn(v.x, v.y);
    __nv_bfloat162 p1 = __floats2bfloat162_rn(v.z, v.w);
    *(uint2*)&out[i*4] = make_uint2(*(unsigned*)&p0, *(unsigned*)&p1);
}

// ---------------- LayerNorm (warp per pixel) -> bf16 ----------------
__global__ void k_ln(const float* __restrict__ x, const float* __restrict__ g,
                     const float* __restrict__ b) {
    int wid = threadIdx.x>>5, lane = threadIdx.x&31;
    int p = blockIdx.x*8 + wid;
    const float* row = x + (size_t)p*CM;
    float s=0.f, s2=0.f;
    for (int c=lane;c<CM;c+=32){ float v=row[c]; s+=v; s2+=v*v; }
    for (int o=16;o;o>>=1){ s+=__shfl_xor_sync(~0u,s,o); s2+=__shfl_xor_sync(~0u,s2,o); }
    float mean = s/CM, var = s2/CM - mean*mean;
    float rstd = rsqrtf(var + 1e-5f);
    for (int c=lane;c<CM;c+=32)
        d_xnb[(size_t)p*CM+c] = __float2bfloat16((row[c]-mean)*rstd*g[c]+b[c]);
}

// ---------------- depthwise 3x3 conv + bias + SiLU (bf16 in/out) ----------------
__global__ __launch_bounds__(256) void k_conv2d_tr(const float* __restrict__ w,
                                                   const float* __restrict__ bias) {
    __shared__ float t[32][33];
    int d0 = blockIdx.x*32, l0 = blockIdx.y*32, b = blockIdx.z;
    int tx = threadIdx.x&31, ty = threadIdx.x>>5;
    #pragma unroll
    for (int r=0;r<4;r++){
        int l = l0 + ty + r*8;
        int h = l>>6, wc = l&63;
        int d = d0 + tx;
        float acc = bias[d];
        #pragma unroll
        for (int dy=0;dy<3;dy++){
            int hh = h+dy-1; if ((unsigned)hh >= 64u) continue;
            #pragma unroll
            for (int dx=0;dx<3;dx++){
                int ww = wc+dx-1; if ((unsigned)ww >= 64u) continue;
                acc = fmaf(w[d*9+dy*3+dx],
                           __bfloat162float(d_xzb[((size_t)(b*LL + (hh<<6)+ww))*(2*DI) + d]), acc);
            }
        }
        float v = acc / (1.f + __expf(-acc));
        d_xsb[(size_t)(b*LL+l)*DI + d] = __float2bfloat16(v);
        t[l-l0][tx] = v;
    }
    __syncthreads();
    #pragma unroll
    for (int r=0;r<4;r++)
        d_utb[((size_t)b*DI + d0+ty+r*8)*LL + l0+tx] = __float2bfloat16(t[tx][ty+r*8]);
}

// ---------------- combine branches + SimpleGate on low B/C ----------------
__global__ void k_combine(const float* __restrict__ w1b, const float* __restrict__ w2b,
                          const float* __restrict__ w1c, const float* __restrict__ w2c) {
    __shared__ float s_w1b[192*16], s_w2b[16*96], s_w1c[192*16], s_w2c[16*96];
    int tid = threadIdx.x;
    for (int i=tid;i<192*16;i+=256){ s_w1b[i]=w1b[i]; s_w1c[i]=w1c[i]; }
    for (int i=tid;i<16*96;i+=256){ s_w2b[i]=w2b[i]; s_w2c[i]=w2c[i]; }
    __syncthreads();
    int gi = blockIdx.x*256 + tid;
    int p = gi>>1, br = gi&1;
    const float* xd = d_xdbl + (size_t)p*64;
    const float* ld = d_ldbl + (size_t)p*64;
    const float* w1 = br? s_w1c : s_w1b;
    const float* w2 = br? s_w2c : s_w2b;
    int off = br? 28 : 12;
    float xv[16], acc[16];
    {
        const float4* l4 = (const float4*)(ld + off);
        #pragma unroll
        for (int q=0;q<4;q++){
            float4 v = l4[q];
            xv[q*4+0]=v.x; xv[q*4+1]=v.y; xv[q*4+2]=v.z; xv[q*4+3]=v.w;
        }
    }
    #pragma unroll
    for (int c=0;c<16;c++) acc[c]=0.f;
    for (int hh=0;hh<96;hh++){
        float y1=0.f, y2=0.f;
        #pragma unroll
        for (int c=0;c<16;c++){
            y1 = fmaf(w1[hh*16+c], xv[c], y1);
            y2 = fmaf(w1[(hh+96)*16+c], xv[c], y2);
        }
        float g = 0.5f*y1*(1.f+erff(y1*0.70710678118f))*y2;
        #pragma unroll
        for (int c=0;c<16;c++) acc[c] = fmaf(g, w2[c*96+hh], acc[c]);
    }
    float* outp = br? d_Cs0 : d_Bs0;
    const float4* x4 = (const float4*)(xd + off);
    #pragma unroll
    for (int q=0;q<4;q++){
        float4 v = x4[q];
        float4 o = make_float4(v.x+acc[q*4+0], v.y+acc[q*4+1],
                               v.z+acc[q*4+2], v.w+acc[q*4+3]);
        *(float4*)&outp[(size_t)p*16 + q*4] = o;
    }
    if (br==0){
        #pragma unroll
        for (int r=0;r<16;r++)
            d_dts0[(size_t)p*16+r] = (r<12)? (xd[r]+ld[r]) : 0.f;
    }
}

// ---------------- residual dilated (dil=2, K=15) depthwise conv1d, float4 ----------------
__global__ void k_dwconv1d(const float* __restrict__ wdt, const float* __restrict__ wB,
                           const float* __restrict__ wC) {
    int idx = blockIdx.x*blockDim.x + threadIdx.x;
    const int per = BD*LL*4;
    int t = idx / per; int rem = idx % per;
    int q = rem & 3; int l = (rem>>2) & (LL-1); int b = rem >> 14;
    const float* in; float* out; const float* w; int nc;
    if (t==0){ in=d_dts0; out=d_dts1; w=wdt; nc=12; }
    else if (t==1){ in=d_Bs0; out=d_Bs1; w=wB; nc=16; }
    else { in=d_Cs0; out=d_Cs1; w=wC; nc=16; }
    size_t base = (size_t)b*LL*16 + q*4;
    int c0 = q*4;
    float4 accv = *(const float4*)&in[base + (size_t)l*16];
    #pragma unroll
    for (int k=0;k<15;k++){
        int ll = l + 2*k - 14;
        if ((unsigned)ll < (unsigned)LL){
            float4 v = *(const float4*)&in[base + (size_t)ll*16];
            float w0 = (c0+0<nc)? w[(c0+0)*15+k] : 0.f;
            float w1 = (c0+1<nc)? w[(c0+1)*15+k] : 0.f;
            float w2 = (c0+2<nc)? w[(c0+2)*15+k] : 0.f;
            float w3 = (c0+3<nc)? w[(c0+3)*15+k] : 0.f;
            accv.x = fmaf(w0, v.x, accv.x);
            accv.y = fmaf(w1, v.y, accv.y);
            accv.z = fmaf(w2, v.z, accv.z);
            accv.w = fmaf(w3, v.w, accv.w);
        }
    }
    *(float4*)&out[base + (size_t)l*16] = accv;
}

// ---------------- selective scan, phase A (fused delta) ----------------
__global__ void k_scanA(const float* __restrict__ A_logs,
                        const float* __restrict__ dtw, const float* __restrict__ dtb) {
    int b = blockIdx.z, chunk = blockIdx.y, ch0 = blockIdx.x*16;
    int tid = threadIdx.x, warp = tid>>5, lane = tid&31, half = lane>>4, n = lane&15;
    int chl = warp*2 + half;
    int d = ch0 + chl;
    float Ac = -expf(A_logs[d*16+n]);
    __shared__ float sB[TT][16], sD[16][TT], sU[16][TT];
    __shared__ float sdts[TT][17];
    __shared__ float sw16[16*12], sb16[16];
    for (int i=tid; i<16*12; i+=256) sw16[i] = dtw[(ch0 + i/12)*12 + (i%12)];
    if (tid < 16) sb16[tid] = dtb[ch0+tid];
    float h = 0.f, ds = 0.f;
    int l0 = chunk*LC;
    for (int t0=0;t0<LC;t0+=TT){
        __syncthreads();
        #pragma unroll
        for (int r=0;r<4;r++){ int j=tid+r*256; int row=j>>4, col=j&15;
            size_t gidx = ((size_t)b*LL + l0+t0+row)*16 + col;
            sB[row][col] = d_Bs1[gidx];
            sdts[row][col] = d_dts1[gidx]; }
        #pragma unroll
        for (int r=0;r<4;r++){ int j=tid+r*256; int ch=j>>6, i=j&63;
            size_t base = ((size_t)b*DI + ch0+ch)*LL + l0+t0;
            sU[ch][i] = __bfloat162float(d_utb[base+i]); }
        __syncthreads();
        #pragma unroll
        for (int r=0;r<4;r++){ int j=tid+r*256; int ch=j>>6, i=j&63;
            float acc = sb16[ch];
            #pragma unroll
            for (int rr=0;rr<12;rr++) acc = fmaf(sdts[i][rr], sw16[ch*12+rr], acc);
            sD[ch][i] = (acc > 20.f)? acc : log1pf(__expf(acc)); }
        __syncthreads();
        #pragma unroll 16
        for (int i=0;i<TT;i++){
            float dly = sD[chl][i], uv = sU[chl][i];
            float a = __expf(dly*Ac);
            h = fmaf(a, h, dly*uv*sB[i][n]);
            ds += dly;
        }
    }
    size_t cb = (size_t)(b*NC+chunk)*DI + d;
    d_hfin[cb*16+n] = h;
    if (n==0) d_dsum[cb] = ds;
}

// ---------------- phase B: stitch chunks ----------------
__global__ void k_scanB(const float* __restrict__ A_logs) {
    int idx = blockIdx.x*blockDim.x + threadIdx.x;
    int n = idx & 15; int d = (idx>>4) % DI; int b = idx/(16*DI);
    float Ac = -expf(A_logs[d*16+n]);
    float H = 0.f;
    for (int c=0;c<NC;c++){
        size_t cb = (size_t)(b*NC+c)*DI + d;
        d_hin[cb*16+n] = H;
        H = __expf(Ac*d_dsum[cb])*H + d_hfin[cb*16+n];
    }
}

// ---------------- phase C: replay (fused delta), emit y bf16 (smem reduce) ----------------
__global__ void k_scanC(const float* __restrict__ A_logs, const float* __restrict__ Ds,
                        const float* __restrict__ dtw, const float* __restrict__ dtb) {
    int b = blockIdx.z, chunk = blockIdx.y, ch0 = blockIdx.x*16;
    int tid = threadIdx.x, warp = tid>>5, lane = tid&31, half = lane>>4, n = lane&15;
    int chl = warp*2 + half;
    int d = ch0 + chl;
    float Ac = -expf(A_logs[d*16+n]);
    size_t cb = (size_t)(b*NC+chunk)*DI + d;
    float h = d_hin[cb*16+n];
    __shared__ float sB[TT][16], sC[TT][16], sD[16][TT], sU[16][TT], sY[TT][16];
    __shared__ float sdts[TT][17];
    __shared__ float sP[16][16*17];
    __shared__ float sDs[16];
    __shared__ float sw16[16*12], sb16[16];
    for (int i=tid; i<16*12; i+=256) sw16[i] = dtw[(ch0 + i/12)*12 + (i%12)];
    if (tid < 16) sb16[tid] = dtb[ch0+tid];
    if (n==0) sDs[chl] = Ds[d];
    int l0 = chunk*LC;
    int chl_o = (tid>>4)&15, i2_o = tid&15;
    for (int t0=0;t0<LC;t0+=TT){
        __syncthreads();
        #pragma unroll
        for (int r=0;r<4;r++){ int j=tid+r*256; int row=j>>4, col=j&15;
            size_t gidx = ((size_t)b*LL + l0+t0+row)*16 + col;
            sB[row][col] = d_Bs1[gidx];
            sC[row][col] = d_Cs1[gidx];
            sdts[row][col] = d_dts1[gidx]; }
        #pragma unroll
        for (int r=0;r<4;r++){ int j=tid+r*256; int ch=j>>6, i=j&63;
            size_t base = ((size_t)b*DI + ch0+ch)*LL + l0+t0;
            sU[ch][i] = __bfloat162float(d_utb[base+i]); }
        __syncthreads();
        #pragma unroll
        for (int r=0;r<4;r++){ int j=tid+r*256; int ch=j>>6, i=j&63;
            float acc = sb16[ch];
            #pragma unroll
            for (int rr=0;rr<12;rr++) acc = fmaf(sdts[i][rr], sw16[ch*12+rr], acc);
            sD[ch][i] = (acc > 20.f)? acc : log1pf(__expf(acc)); }
        __syncthreads();
        #pragma unroll
        for (int ii=0; ii<4; ii++){
            #pragma unroll
            for (int i2=0;i2<16;i2++){
                int i = ii*16 + i2;
                float dly = sD[chl][i], uv = sU[chl][i];
                float a = __expf(dly*Ac);
                h = fmaf(a, h, dly*uv*sB[i][n]);
                sP[chl][i2*17+n] = h * sC[i][n];
            }
            __syncthreads();
            {
                float s = 0.f;
                #pragma unroll
                for (int nn=0;nn<16;nn++) s += sP[chl_o][i2_o*17+nn];
                int io = ii*16 + i2_o;
                sY[io][chl_o] = s + sU[chl_o][io]*sDs[chl_o];
            }
            __syncthreads();
        }
        #pragma unroll
        for (int r=0;r<4;r++){ int j=tid+r*256; int row=j>>4, col=j&15;
            d_yb[((size_t)b*LL + l0+t0+row)*DI + ch0+col] = __float2bfloat16(sY[row][col]); }
    }
}

// ---------------- out_norm LN * silu(z) -> bf16 (warp per pixel; y,z from bf16) ----------------
__global__ void k_gate(const float* __restrict__ g, const float* __restrict__ bb) {
    int wid = threadIdx.x>>5, lane = threadIdx.x&31;
    int p = blockIdx.x*8 + wid;
    const __nv_bfloat16* yrow = d_yb + (size_t)p*DI;
    const __nv_bfloat16* zrow = d_xzb + (size_t)p*(2*DI) + DI;
    const float4* g4   = (const float4*)g;
    const float4* b4   = (const float4*)bb;
    float v[3][4];
    float s=0.f, s2=0.f;
    #pragma unroll
    for (int q=0;q<3;q++){
        int i4 = lane + q*32;
        uint2 yb = *(const uint2*)&yrow[i4*4];
        __nv_bfloat162 yp0 = *(__nv_bfloat162*)&yb.x;
        __nv_bfloat162 yp1 = *(__nv_bfloat162*)&yb.y;
        v[q][0] = __bfloat162float(__low2bfloat16(yp0));
        v[q][1] = __bfloat162float(__high2bfloat16(yp0));
        v[q][2] = __bfloat162float(__low2bfloat16(yp1));
        v[q][3] = __bfloat162float(__high2bfloat16(yp1));
        #pragma unroll
        for (int e=0;e<4;e++){ s += v[q][e]; s2 += v[q][e]*v[q][e]; }
    }
    for (int o=16;o;o>>=1){ s+=__shfl_xor_sync(~0u,s,o); s2+=__shfl_xor_sync(~0u,s2,o); }
    float mean = s/DI, var = s2/DI - mean*mean;
    float rstd = rsqrtf(var + 1e-5f);
    __nv_bfloat16* outb = d_gatedb + (size_t)p*DI;
    #pragma unroll
    for (int q=0;q<3;q++){
        int i4 = lane + q*32;
        uint2 zb = *(const uint2*)&zrow[i4*4];
        __nv_bfloat162 zp0 = *(__nv_bfloat162*)&zb.x;
        __nv_bfloat162 zp1 = *(__nv_bfloat162*)&zb.y;
        float z0 = __bfloat162float(__low2bfloat16(zp0));
        float z1 = __bfloat162float(__high2bfloat16(zp0));
        float z2 = __bfloat162float(__low2bfloat16(zp1));
        float z3 = __bfloat162float(__high2bfloat16(zp1));
        float4 gg = g4[i4], bv = b4[i4];
        float o0,o1,o2,o3, yn;
        yn = (v[q][0]-mean)*rstd*gg.x+bv.x; o0 = yn*(z0/(1.f+__expf(-z0)));
        yn = (v[q][1]-mean)*rstd*gg.y+bv.y; o1 = yn*(z1/(1.f+__expf(-z1)));
        yn = (v[q][2]-mean)*rstd*gg.z+bv.z; o2 = yn*(z2/(1.f+__expf(-z2)));
        yn = (v[q][3]-mean)*rstd*gg.w+bv.w; o3 = yn*(z3/(1.f+__expf(-z3)));
        __nv_bfloat162 p0 = __floats2bfloat162_rn(o0, o1);
        __nv_bfloat162 p1 = __floats2bfloat162_rn(o2, o3);
        *(uint2*)&outb[i4*4] = make_uint2(*(unsigned*)&p0, *(unsigned*)&p1);
    }
}

// ---------------- launcher ----------------
extern "C" void kernel_launch(void* const* d_in, const int* in_sizes, int n_in,
                              void* d_out, int out_size) {
    const float* x    = (const float*)d_in[0];
    const float* low  = (const float*)d_in[1];
    const float* ln_g = (const float*)d_in[2];
    const float* ln_b = (const float*)d_in[3];
    const float* ipw  = (const float*)d_in[4];
    const float* iplw = (const float*)d_in[5];
    const float* c2w  = (const float*)d_in[6];
    const float* c2b  = (const float*)d_in[7];
    const float* xpw  = (const float*)d_in[8];
    const float* xpwl = (const float*)d_in[9];
    const float* cdtw = (const float*)d_in[10];
    const float* cBw  = (const float*)d_in[11];
    const float* cCw  = (const float*)d_in[12];
    const float* sgbw1= (const float*)d_in[13];
    const float* sgbw2= (const float*)d_in[14];
    const float* sgcw1= (const float*)d_in[15];
    const float* sgcw2= (const float*)d_in[16];
    const float* dtw  = (const float*)d_in[17];
    const float* dtb  = (const float*)d_in[18];
    const float* Alog = (const float*)d_in[19];
    const float* Ds   = (const float*)d_in[20];
    const float* ong  = (const float*)d_in[21];
    const float* onb  = (const float*)d_in[22];
    const float* opw  = (const float*)d_in[23];
    float* out = (float*)d_out;

    void *p_xnb, *p_lowb, *p_xzb, *p_lowpb, *p_xsb, *p_xdbl, *p_ldbl, *p_gatedb;
    void *p_W1b, *p_W2b, *p_W3b, *p_Wtxb, *p_Wtxlb;
    cudaGetSymbolAddress(&p_xnb, d_xnb);
    cudaGetSymbolAddress(&p_lowb, d_lowb);
    cudaGetSymbolAddress(&p_xzb, d_xzb);
    cudaGetSymbolAddress(&p_lowpb, d_lowpb);
    cudaGetSymbolAddress(&p_xsb, d_xsb);
    cudaGetSymbolAddress(&p_xdbl, d_xdbl);
    cudaGetSymbolAddress(&p_ldbl, d_ldbl);
    cudaGetSymbolAddress(&p_gatedb, d_gatedb);
    cudaGetSymbolAddress(&p_W1b, d_W1b);
    cudaGetSymbolAddress(&p_W2b, d_W2b);
    cudaGetSymbolAddress(&p_W3b, d_W3b);
    cudaGetSymbolAddress(&p_Wtxb, d_Wtxb);
    cudaGetSymbolAddress(&p_Wtxlb, d_Wtxlb);

    static cudaStream_t s2 = nullptr;
    static cudaEvent_t evP = nullptr, evLow = nullptr;
    if (!s2){
        cudaStreamCreateWithFlags(&s2, cudaStreamNonBlocking);
        cudaEventCreateWithFlags(&evP,   cudaEventDisableTiming);
        cudaEventCreateWithFlags(&evLow, cudaEventDisableTiming);
    }

    // 1) weight prep
    k_prep<<<(2*DI*CM + DI*CM + CM*DI + 2*64*DI + 255)/256, 256>>>(ipw, iplw, opw, xpw, xpwl);
    cudaEventRecord(evP, 0);
    // 2) pre-LN -> bf16
    k_ln<<<PX/8, 256>>>(x, ln_g, ln_b);
    // 3) convert low -> bf16 (side stream)
    cudaStreamWaitEvent(s2, evP, 0);
    k_tobf<<<(PX*CM/4 + 255)/256, 256, 0, s2>>>(low, (__nv_bfloat16*)p_lowb, PX*CM/4);
    // 4) in_proj -> bf16 xz (main) <-- profiled
    k_gemm_bf16<<<dim3(768/64, PX/128), 256>>>((const __nv_bfloat16*)p_xnb,
        (const __nv_bfloat16*)p_W1b, nullptr, (__nv_bfloat16*)p_xzb, CM, 2*DI, nullptr);
    // 5) in_proj_low -> bf16 only (side)
    k_gemm_bf16<<<dim3(DI/64, PX/128), 256, 0, s2>>>((const __nv_bfloat16*)p_lowb,
        (const __nv_bfloat16*)p_W2b, nullptr, (__nv_bfloat16*)p_lowpb, CM, DI, nullptr);
    // 6) x_proj low (bf16, side)
    k_gemm_bf16<<<dim3(1, PX/128), 256, 0, s2>>>((const __nv_bfloat16*)p_lowpb,
        (const __nv_bfloat16*)p_Wtxlb, (float*)p_ldbl, nullptr, DI, 64, nullptr);
    cudaEventRecord(evLow, s2);

    // main: conv+silu -> bf16 pixel-major + bf16 channel-major
    k_conv2d_tr<<<dim3(DI/32, LL/32, BD), 256>>>(c2w, c2b);
    // x_proj high (bf16)
    k_gemm_bf16<<<dim3(1, PX/128), 256>>>((const __nv_bfloat16*)p_xsb,
        (const __nv_bfloat16*)p_Wtxb, (float*)p_xdbl, nullptr, DI, 64, nullptr);
    cudaStreamWaitEvent(0, evLow, 0);
    k_combine<<<2*PX/256, 256>>>(sgbw1, sgbw2, sgcw1, sgcw2);
    k_dwconv1d<<<3*BD*LL*4/256, 256>>>(cdtw, cBw, cCw);
    k_scanA<<<dim3(DI/16, NC, BD), 256>>>(Alog, dtw, dtb);
    k_scanB<<<BD*DI*16/256, 256>>>(Alog);
    k_scanC<<<dim3(DI/16, NC, BD), 256>>>(Alog, Ds, dtw, dtb);
    k_gate<<<PX/8, 256>>>(ong, onb);
    // out_proj (+resid x)
    k_gemm_bf16<<<dim3(CM/64, PX/128), 256>>>((const __nv_bfloat16*)p_gatedb,
        (const __nv_bfloat16*)p_W3b, out, nullptr, DI, CM, x);
}